// round 10
// baseline (speedup 1.0000x reference)
#include <cuda_runtime.h>
#include <cuda_fp16.h>
#include <cuda_bf16.h>
#include <mma.h>

using namespace nvcuda;

#define BATCH 256
#define HID   1024
#define TLEN  256
#define KDIM  2048            // concat(h, c)
#define NGATE 4096
#define NTOT  5120            // 4 gates + fc columns (row-permuted)
#define NCTA  128             // 2 M-tiles x 64 hid-tiles
#define NTHR  128
#define NK    32              // 2048 / 64 K-chunks
#define BK    64

// ---------------- scratch (static device globals; no allocations) ----------
__device__ __half g_Wperm[(size_t)NTOT * KDIM];   // 20 MB permuted combined weights (fp16)
__device__ __half g_Wih_h[(size_t)NGATE * HID];   // 8 MB
__device__ __half g_Wfc_h[(size_t)HID * HID];     // 2 MB
__device__ __half g_x[2][(size_t)BATCH * KDIM];   // 2 MB double-buffered activations
__device__ float  g_b0[NGATE];                    // b_ih + b_hh            (iter 0)
__device__ float  g_bcomb[NGATE];                 // b0 + W_ih @ b_fc       (iter >=1)
__device__ unsigned int g_bar;

// ---------------- small helpers -------------------------------------------
__device__ __forceinline__ void cp16(void* dst, const void* src) {
    unsigned sdst = (unsigned)__cvta_generic_to_shared(dst);
    asm volatile("cp.async.cg.shared.global [%0], [%1], 16;\n" :: "r"(sdst), "l"(src));
}
__device__ __forceinline__ void cp_commit() { asm volatile("cp.async.commit_group;\n"); }
template<int N> __device__ __forceinline__ void cp_wait() {
    asm volatile("cp.async.wait_group %0;\n" :: "n"(N));
}
__device__ __forceinline__ float sigf(float x) { return 1.f / (1.f + __expf(-x)); }

// ---------------- prep kernels --------------------------------------------
__global__ void k_init(const float* __restrict__ c_vec,
                       const float* __restrict__ b_ih,
                       const float* __restrict__ b_hh) {
    int stride = gridDim.x * blockDim.x;
    int i0 = blockIdx.x * blockDim.x + threadIdx.x;
    if (i0 == 0) g_bar = 0u;
    for (int idx = i0; idx < BATCH * KDIM; idx += stride) {
        int k = idx & (KDIM - 1);
        int b = idx >> 11;
        g_x[0][idx] = (k < HID) ? __float2half(c_vec[b * HID + k]) : __float2half(0.f);
    }
    for (int n = i0; n < NGATE; n += stride) g_b0[n] = b_ih[n] + b_hh[n];
}

__global__ void k_convert(const float* __restrict__ W_ih,
                          const float* __restrict__ W_fc) {
    size_t stride = (size_t)gridDim.x * blockDim.x;
    size_t i0 = (size_t)blockIdx.x * blockDim.x + threadIdx.x;
    for (size_t i = i0; i < (size_t)NGATE * HID; i += stride) g_Wih_h[i] = __float2half(W_ih[i]);
    for (size_t i = i0; i < (size_t)HID * HID; i += stride)  g_Wfc_h[i] = __float2half(W_fc[i]);
}

// Fill the permuted weight matrix: row p = ht*80 + g*16 + (hid%16), hid = ht*16 + (p%16...)
//   g<4 (gate rows):  k<1024 -> W_hh[n][k]          (upper K half written by k_wcomb)
//   g==4 (fc rows):   k<1024 -> 0 ; k>=1024 -> W_fc[hid][k-1024]
__global__ void k_fill(const float* __restrict__ W_hh,
                       const float* __restrict__ W_fc) {
    long stride = (long)gridDim.x * blockDim.x;
    for (long idx = (long)blockIdx.x * blockDim.x + threadIdx.x;
         idx < (long)NTOT * KDIM; idx += stride) {
        int k = (int)(idx & (KDIM - 1));
        int p = (int)(idx >> 11);
        int r = p % 80, ht = p / 80;
        int g = r >> 4, hid = ht * 16 + (r & 15);
        if (g < 4) {
            if (k < HID)
                g_Wperm[idx] = __float2half(W_hh[(size_t)(g * HID + hid) * HID + k]);
        } else {
            g_Wperm[idx] = (k < HID) ? __float2half(0.f)
                                     : __float2half(W_fc[(size_t)hid * HID + (k - HID)]);
        }
    }
}

// b_comb[n] = b0[n] + sum_j W_ih[n][j] * b_fc[j]   (one warp per row)
__global__ void k_bcomb(const float* __restrict__ W_ih,
                        const float* __restrict__ b_fc) {
    int warp = (blockIdx.x * blockDim.x + threadIdx.x) >> 5;
    int lane = threadIdx.x & 31;
    if (warp >= NGATE) return;
    const float* wrow = W_ih + (size_t)warp * HID;
    float s = 0.f;
    for (int j = lane; j < HID; j += 32) s += wrow[j] * b_fc[j];
    #pragma unroll
    for (int off = 16; off; off >>= 1) s += __shfl_xor_sync(0xffffffffu, s, off);
    if (lane == 0) g_bcomb[warp] = g_b0[warp] + s;
}

// W_comb = W_ih @ W_fc  -> fp16, written directly into permuted upper-K slots.
// C[n][h] = sum_o Wih[n][o] * Wfc[o][h].  Tiles 64x64x64, 4 warps of 32x32.
__global__ void __launch_bounds__(128) k_wcomb() {
    __shared__ union {
        struct { __half A[2][64][72]; __half B[2][64][72]; } g;
        float stage[64][68];   // ldm 68: multiple of 4 floats (WMMA 16B rule)
    } sm;
    const int tid = threadIdx.x;
    const int w = tid >> 5;
    const int bn = blockIdx.x;            // 0..15  (h tiles)
    const int bm = blockIdx.y;            // 0..63  (n tiles)
    const int m0 = (w >> 1) * 32;
    const int n0 = (w & 1) * 32;

    wmma::fragment<wmma::accumulator, 16, 16, 16, float> acc[2][2];
    #pragma unroll
    for (int a = 0; a < 2; a++)
        #pragma unroll
        for (int b = 0; b < 2; b++) wmma::fill_fragment(acc[a][b], 0.f);

    auto load_chunk = [&](int kc, int bufn) {
        #pragma unroll
        for (int i = 0; i < 4; i++) {
            int idx = i * 128 + tid, row = idx >> 3, seg = idx & 7;
            cp16(&sm.g.A[bufn][row][seg * 8],
                 g_Wih_h + (size_t)(bm * 64 + row) * HID + kc * 64 + seg * 8);
            cp16(&sm.g.B[bufn][row][seg * 8],
                 g_Wfc_h + (size_t)(kc * 64 + row) * HID + bn * 64 + seg * 8);
        }
    };
    load_chunk(0, 0); cp_commit();
    int buf = 0;
    for (int kc = 0; kc < 16; kc++) {
        if (kc < 15) { load_chunk(kc + 1, buf ^ 1); cp_commit(); cp_wait<1>(); }
        else         { cp_wait<0>(); }
        __syncthreads();
        #pragma unroll
        for (int kk = 0; kk < 4; kk++) {
            wmma::fragment<wmma::matrix_a, 16, 16, 16, __half, wmma::row_major> fa[2];
            wmma::fragment<wmma::matrix_b, 16, 16, 16, __half, wmma::row_major> fb[2];
            wmma::load_matrix_sync(fa[0], &sm.g.A[buf][m0][kk * 16], 72);
            wmma::load_matrix_sync(fa[1], &sm.g.A[buf][m0 + 16][kk * 16], 72);
            wmma::load_matrix_sync(fb[0], &sm.g.B[buf][kk * 16][n0], 72);
            wmma::load_matrix_sync(fb[1], &sm.g.B[buf][kk * 16][n0 + 16], 72);
            #pragma unroll
            for (int a = 0; a < 2; a++)
                #pragma unroll
                for (int b = 0; b < 2; b++)
                    wmma::mma_sync(acc[a][b], fa[a], fb[b], acc[a][b]);
        }
        __syncthreads();
        buf ^= 1;
    }
    #pragma unroll
    for (int a = 0; a < 2; a++)
        #pragma unroll
        for (int b = 0; b < 2; b++)
            wmma::store_matrix_sync(&sm.stage[m0 + a * 16][n0 + b * 16], acc[a][b], 68,
                                    wmma::mem_row_major);
    __syncthreads();
    #pragma unroll
    for (int it = 0; it < 32; it++) {
        int idx = it * 128 + tid, r = idx >> 6, cc = idx & 63;
        int n = bm * 64 + r, h = bn * 64 + cc;
        int g = n >> 10, hid = n & 1023;
        int p = (hid >> 4) * 80 + (g << 4) + (hid & 15);
        g_Wperm[(size_t)p * KDIM + HID + h] = __float2half(sm.stage[r][cc]);
    }
}

// ---------------- main persistent kernel ----------------------------------
struct MainSmem {
    union {
        struct { __half A[2][128][72]; __half B[2][80][72]; } g;   // 59904 B
        float stage[128][84];   // ldm 84: multiple of 4 floats (WMMA 16B rule)
    } u;
    float c_sm[128][16];                                           // fp32 master cell state
    float bias0[64], biasN[64], biasFC[16];
};

__global__ void __launch_bounds__(NTHR, 1)
k_main(const float* __restrict__ c_vec, const float* __restrict__ b_fc,
       float* __restrict__ out) {
    extern __shared__ char smraw[];
    MainSmem& sm = *reinterpret_cast<MainSmem*>(smraw);
    const int tid = threadIdx.x;
    const int w = tid >> 5;
    const int bx = blockIdx.x;
    const int mt = bx >> 6;          // 0..1   (batch half)
    const int ht = bx & 63;          // 0..63  (hidden slice of 16)
    const int hid0 = ht * 16;
    const int warpM = w * 32;

    if (tid < 64) {
        int g = tid >> 4, j = tid & 15;
        sm.bias0[tid] = g_b0[g * HID + hid0 + j];
        sm.biasN[tid] = g_bcomb[g * HID + hid0 + j];
    }
    if (tid < 16) sm.biasFC[tid] = b_fc[hid0 + tid];
    {
        const float* crow = c_vec + (size_t)(mt * 128 + tid) * HID + hid0;
        #pragma unroll
        for (int j = 0; j < 16; j++) sm.c_sm[tid][j] = crow[j];
    }
    __syncthreads();

    const __half* Bglob = g_Wperm + (size_t)(ht * 80) * KDIM;
    float* hs = out;
    float* cs = out + (size_t)BATCH * TLEN * HID;
    float* os = out + (size_t)2 * BATCH * TLEN * HID;

    for (int t = 0; t <= TLEN; t++) {
        const __half* Aglob = g_x[t & 1] + (size_t)(mt * 128) * KDIM;

        wmma::fragment<wmma::accumulator, 16, 16, 16, float> acc[2][5];
        #pragma unroll
        for (int a = 0; a < 2; a++)
            #pragma unroll
            for (int b = 0; b < 5; b++) wmma::fill_fragment(acc[a][b], 0.f);

        auto load_chunk = [&](int kc, int bufn) {
            #pragma unroll
            for (int i = 0; i < 8; i++) {
                int idx = i * 128 + tid, row = idx >> 3, seg = idx & 7;
                cp16(&sm.u.g.A[bufn][row][seg * 8],
                     Aglob + (size_t)row * KDIM + kc * 64 + seg * 8);
            }
            #pragma unroll
            for (int i = 0; i < 5; i++) {
                int idx = i * 128 + tid, row = idx >> 3, seg = idx & 7;
                cp16(&sm.u.g.B[bufn][row][seg * 8],
                     Bglob + (size_t)row * KDIM + kc * 64 + seg * 8);
            }
        };

        load_chunk(0, 0); cp_commit();
        int buf = 0;
        for (int kc = 0; kc < NK; kc++) {
            if (kc < NK - 1) { load_chunk(kc + 1, buf ^ 1); cp_commit(); cp_wait<1>(); }
            else             { cp_wait<0>(); }
            __syncthreads();
            #pragma unroll
            for (int kk = 0; kk < 4; kk++) {
                wmma::fragment<wmma::matrix_a, 16, 16, 16, __half, wmma::row_major> fa0, fa1;
                wmma::load_matrix_sync(fa0, &sm.u.g.A[buf][warpM][kk * 16], 72);
                wmma::load_matrix_sync(fa1, &sm.u.g.A[buf][warpM + 16][kk * 16], 72);
                #pragma unroll
                for (int nf = 0; nf < 5; nf++) {
                    wmma::fragment<wmma::matrix_b, 16, 16, 16, __half, wmma::col_major> fb;
                    wmma::load_matrix_sync(fb, &sm.u.g.B[buf][nf * 16][kk * 16], 72);
                    wmma::mma_sync(acc[0][nf], fa0, fb, acc[0][nf]);
                    wmma::mma_sync(acc[1][nf], fa1, fb, acc[1][nf]);
                }
            }
            __syncthreads();
            buf ^= 1;
        }

        // ---- epilogue: stage accumulators, do LSTM cell update CTA-locally ----
        #pragma unroll
        for (int a = 0; a < 2; a++)
            #pragma unroll
            for (int nf = 0; nf < 5; nf++)
                wmma::store_matrix_sync(&sm.u.stage[warpM + a * 16][nf * 16], acc[a][nf], 84,
                                        wmma::mem_row_major);
        __syncthreads();

        {
            const int r = tid;
            const int b = mt * 128 + r;
            const float* srow = &sm.u.stage[r][0];
            if (t < TLEN) {
                __half* xn = g_x[(t + 1) & 1] + (size_t)b * KDIM;
                size_t ob = (size_t)b * (TLEN * HID) + (size_t)t * HID + hid0;
                #pragma unroll
                for (int j = 0; j < 16; j++) {
                    float bi, bff, bg, bo;
                    if (t == 0) { bi = sm.bias0[j];      bff = sm.bias0[16 + j];
                                  bg = sm.bias0[32 + j]; bo  = sm.bias0[48 + j]; }
                    else        { bi = sm.biasN[j];      bff = sm.biasN[16 + j];
                                  bg = sm.biasN[32 + j]; bo  = sm.biasN[48 + j]; }
                    float gi = srow[j]      + bi;
                    float gf = srow[16 + j] + bff;
                    float gg = srow[32 + j] + bg;
                    float go = srow[48 + j] + bo;
                    float c_old = sm.c_sm[r][j];
                    float c_new = sigf(gf) * c_old + sigf(gi) * tanhf(gg);
                    float h_new = sigf(go) * tanhf(c_new);
                    sm.c_sm[r][j] = c_new;
                    hs[ob + j] = h_new;
                    cs[ob + j] = c_new;
                    xn[hid0 + j]       = __float2half(h_new);
                    xn[HID + hid0 + j] = __float2half(c_new);
                }
            }
            if (t >= 1) {
                size_t ob2 = (size_t)b * (TLEN * HID) + (size_t)(t - 1) * HID + hid0;
                #pragma unroll
                for (int j = 0; j < 16; j++) os[ob2 + j] = srow[64 + j] + sm.biasFC[j];
            }
        }

        // ---- grid barrier (skip after last iteration) ----
        if (t < TLEN) {
            __threadfence();
            __syncthreads();
            if (tid == 0) {
                atomicAdd(&g_bar, 1u);
                unsigned target = (unsigned)NCTA * (unsigned)(t + 1);
                while (*((volatile unsigned int*)&g_bar) < target) __nanosleep(128);
            }
            __syncthreads();
        }
    }
}

// ---------------- host entry ----------------------------------------------
extern "C" void kernel_launch(void* const* d_in, const int* in_sizes, int n_in,
                              void* d_out, int out_size) {
    const float* c_vec = (const float*)d_in[0];
    const float* W_ih  = (const float*)d_in[1];
    const float* W_hh  = (const float*)d_in[2];
    const float* b_ih  = (const float*)d_in[3];
    const float* b_hh  = (const float*)d_in[4];
    const float* W_fc  = (const float*)d_in[5];
    const float* b_fc  = (const float*)d_in[6];
    float* out = (float*)d_out;

    cudaFuncSetAttribute(k_main, cudaFuncAttributeMaxDynamicSharedMemorySize,
                         (int)sizeof(MainSmem));

    k_init<<<256, 256>>>(c_vec, b_ih, b_hh);
    k_convert<<<256, 256>>>(W_ih, W_fc);
    k_fill<<<512, 256>>>(W_hh, W_fc);
    k_bcomb<<<512, 256>>>(W_ih, b_fc);
    k_wcomb<<<dim3(16, 64), 128>>>();
    k_main<<<NCTA, NTHR, sizeof(MainSmem)>>>(c_vec, b_fc, out);
}

// round 11
// speedup vs baseline: 1.0100x; 1.0100x over previous
#include <cuda_runtime.h>
#include <cuda_fp16.h>
#include <cuda_bf16.h>
#include <mma.h>

using namespace nvcuda;

#define BATCH 256
#define HID   1024
#define TLEN  256
#define KDIM  2048            // concat(h, c)
#define NGATE 4096
#define NTOT  5120            // 4 gates + fc columns (row-permuted)
#define NCTA  128             // 2 M-tiles x 64 hid-tiles
#define NTHR  128
#define NK    32              // 2048 / 64 K-chunks
#define BK    64

// ---------------- scratch (static device globals; no allocations) ----------
__device__ __half g_Wperm[(size_t)NTOT * KDIM];   // 20 MB permuted combined weights (fp16)
__device__ __half g_Wih_h[(size_t)NGATE * HID];   // 8 MB
__device__ __half g_Wfc_h[(size_t)HID * HID];     // 2 MB
__device__ __half g_x[2][(size_t)BATCH * KDIM];   // 2 MB double-buffered activations
__device__ float  g_b0[NGATE];                    // b_ih + b_hh            (iter 0)
__device__ float  g_bcomb[NGATE];                 // b0 + W_ih @ b_fc       (iter >=1)
__device__ unsigned int g_bar;

// ---------------- small helpers -------------------------------------------
__device__ __forceinline__ void cp16(void* dst, const void* src) {
    unsigned sdst = (unsigned)__cvta_generic_to_shared(dst);
    asm volatile("cp.async.cg.shared.global [%0], [%1], 16;\n" :: "r"(sdst), "l"(src));
}
__device__ __forceinline__ void cp_commit() { asm volatile("cp.async.commit_group;\n"); }
template<int N> __device__ __forceinline__ void cp_wait() {
    asm volatile("cp.async.wait_group %0;\n" :: "n"(N));
}
__device__ __forceinline__ float sigf(float x) { return 1.f / (1.f + __expf(-x)); }

// ---------------- prep kernels --------------------------------------------
__global__ void k_init(const float* __restrict__ c_vec,
                       const float* __restrict__ b_ih,
                       const float* __restrict__ b_hh) {
    int stride = gridDim.x * blockDim.x;
    int i0 = blockIdx.x * blockDim.x + threadIdx.x;
    if (i0 == 0) g_bar = 0u;
    for (int idx = i0; idx < BATCH * KDIM; idx += stride) {
        int k = idx & (KDIM - 1);
        int b = idx >> 11;
        g_x[0][idx] = (k < HID) ? __float2half(c_vec[b * HID + k]) : __float2half(0.f);
    }
    for (int n = i0; n < NGATE; n += stride) g_b0[n] = b_ih[n] + b_hh[n];
}

__global__ void k_convert(const float* __restrict__ W_ih,
                          const float* __restrict__ W_fc) {
    size_t stride = (size_t)gridDim.x * blockDim.x;
    size_t i0 = (size_t)blockIdx.x * blockDim.x + threadIdx.x;
    for (size_t i = i0; i < (size_t)NGATE * HID; i += stride) g_Wih_h[i] = __float2half(W_ih[i]);
    for (size_t i = i0; i < (size_t)HID * HID; i += stride)  g_Wfc_h[i] = __float2half(W_fc[i]);
}

// Fill the permuted weight matrix: row p = ht*80 + g*16 + (hid%16), hid = ht*16 + (p%16...)
//   g<4 (gate rows):  k<1024 -> W_hh[n][k]          (upper K half written by k_wcomb)
//   g==4 (fc rows):   k<1024 -> 0 ; k>=1024 -> W_fc[hid][k-1024]
__global__ void k_fill(const float* __restrict__ W_hh,
                       const float* __restrict__ W_fc) {
    long stride = (long)gridDim.x * blockDim.x;
    for (long idx = (long)blockIdx.x * blockDim.x + threadIdx.x;
         idx < (long)NTOT * KDIM; idx += stride) {
        int k = (int)(idx & (KDIM - 1));
        int p = (int)(idx >> 11);
        int r = p % 80, ht = p / 80;
        int g = r >> 4, hid = ht * 16 + (r & 15);
        if (g < 4) {
            if (k < HID)
                g_Wperm[idx] = __float2half(W_hh[(size_t)(g * HID + hid) * HID + k]);
        } else {
            g_Wperm[idx] = (k < HID) ? __float2half(0.f)
                                     : __float2half(W_fc[(size_t)hid * HID + (k - HID)]);
        }
    }
}

// b_comb[n] = b0[n] + sum_j W_ih[n][j] * b_fc[j]   (one warp per row)
__global__ void k_bcomb(const float* __restrict__ W_ih,
                        const float* __restrict__ b_fc) {
    int warp = (blockIdx.x * blockDim.x + threadIdx.x) >> 5;
    int lane = threadIdx.x & 31;
    if (warp >= NGATE) return;
    const float* wrow = W_ih + (size_t)warp * HID;
    float s = 0.f;
    for (int j = lane; j < HID; j += 32) s += wrow[j] * b_fc[j];
    #pragma unroll
    for (int off = 16; off; off >>= 1) s += __shfl_xor_sync(0xffffffffu, s, off);
    if (lane == 0) g_bcomb[warp] = g_b0[warp] + s;
}

// W_comb = W_ih @ W_fc  -> fp16, written directly into permuted upper-K slots.
// C[n][h] = sum_o Wih[n][o] * Wfc[o][h].  Tiles 64x64x64, 4 warps of 32x32.
__global__ void __launch_bounds__(128) k_wcomb() {
    __shared__ union {
        struct { __half A[2][64][72]; __half B[2][64][72]; } g;
        float stage[64][68];   // ldm 68: multiple of 4 floats (WMMA 16B rule)
    } sm;
    const int tid = threadIdx.x;
    const int w = tid >> 5;
    const int bn = blockIdx.x;            // 0..15  (h tiles)
    const int bm = blockIdx.y;            // 0..63  (n tiles)
    const int m0 = (w >> 1) * 32;
    const int n0 = (w & 1) * 32;

    wmma::fragment<wmma::accumulator, 16, 16, 16, float> acc[2][2];
    #pragma unroll
    for (int a = 0; a < 2; a++)
        #pragma unroll
        for (int b = 0; b < 2; b++) wmma::fill_fragment(acc[a][b], 0.f);

    auto load_chunk = [&](int kc, int bufn) {
        #pragma unroll
        for (int i = 0; i < 4; i++) {
            int idx = i * 128 + tid, row = idx >> 3, seg = idx & 7;
            cp16(&sm.g.A[bufn][row][seg * 8],
                 g_Wih_h + (size_t)(bm * 64 + row) * HID + kc * 64 + seg * 8);
            cp16(&sm.g.B[bufn][row][seg * 8],
                 g_Wfc_h + (size_t)(kc * 64 + row) * HID + bn * 64 + seg * 8);
        }
    };
    load_chunk(0, 0); cp_commit();
    int buf = 0;
    for (int kc = 0; kc < 16; kc++) {
        if (kc < 15) { load_chunk(kc + 1, buf ^ 1); cp_commit(); cp_wait<1>(); }
        else         { cp_wait<0>(); }
        __syncthreads();
        #pragma unroll
        for (int kk = 0; kk < 4; kk++) {
            wmma::fragment<wmma::matrix_a, 16, 16, 16, __half, wmma::row_major> fa[2];
            wmma::fragment<wmma::matrix_b, 16, 16, 16, __half, wmma::row_major> fb[2];
            wmma::load_matrix_sync(fa[0], &sm.g.A[buf][m0][kk * 16], 72);
            wmma::load_matrix_sync(fa[1], &sm.g.A[buf][m0 + 16][kk * 16], 72);
            wmma::load_matrix_sync(fb[0], &sm.g.B[buf][kk * 16][n0], 72);
            wmma::load_matrix_sync(fb[1], &sm.g.B[buf][kk * 16][n0 + 16], 72);
            #pragma unroll
            for (int a = 0; a < 2; a++)
                #pragma unroll
                for (int b = 0; b < 2; b++)
                    wmma::mma_sync(acc[a][b], fa[a], fb[b], acc[a][b]);
        }
        __syncthreads();
        buf ^= 1;
    }
    #pragma unroll
    for (int a = 0; a < 2; a++)
        #pragma unroll
        for (int b = 0; b < 2; b++)
            wmma::store_matrix_sync(&sm.stage[m0 + a * 16][n0 + b * 16], acc[a][b], 68,
                                    wmma::mem_row_major);
    __syncthreads();
    #pragma unroll
    for (int it = 0; it < 32; it++) {
        int idx = it * 128 + tid, r = idx >> 6, cc = idx & 63;
        int n = bm * 64 + r, h = bn * 64 + cc;
        int g = n >> 10, hid = n & 1023;
        int p = (hid >> 4) * 80 + (g << 4) + (hid & 15);
        g_Wperm[(size_t)p * KDIM + HID + h] = __float2half(sm.stage[r][cc]);
    }
}

// ---------------- main persistent kernel ----------------------------------
struct MainSmem {
    union {
        struct { __half A[2][128][72]; __half B[2][80][72]; } g;   // 59904 B
        float stage[128][84];   // ldm 84: multiple of 4 floats (WMMA 16B rule)
    } u;
    float c_sm[128][16];                                           // fp32 master cell state
    float bias0[64], biasN[64], biasFC[16];
};

__global__ void __launch_bounds__(NTHR, 1)
k_main(const float* __restrict__ c_vec, const float* __restrict__ b_fc,
       float* __restrict__ out) {
    extern __shared__ char smraw[];
    MainSmem& sm = *reinterpret_cast<MainSmem*>(smraw);
    const int tid = threadIdx.x;
    const int w = tid >> 5;
    const int bx = blockIdx.x;
    const int mt = bx >> 6;          // 0..1   (batch half)
    const int ht = bx & 63;          // 0..63  (hidden slice of 16)
    const int hid0 = ht * 16;
    const int warpM = w * 32;

    if (tid < 64) {
        int g = tid >> 4, j = tid & 15;
        sm.bias0[tid] = g_b0[g * HID + hid0 + j];
        sm.biasN[tid] = g_bcomb[g * HID + hid0 + j];
    }
    if (tid < 16) sm.biasFC[tid] = b_fc[hid0 + tid];
    {
        const float* crow = c_vec + (size_t)(mt * 128 + tid) * HID + hid0;
        #pragma unroll
        for (int j = 0; j < 16; j++) sm.c_sm[tid][j] = crow[j];
    }
    __syncthreads();

    const __half* Bglob = g_Wperm + (size_t)(ht * 80) * KDIM;
    float* hs = out;
    float* cs = out + (size_t)BATCH * TLEN * HID;
    float* os = out + (size_t)2 * BATCH * TLEN * HID;

    for (int t = 0; t <= TLEN; t++) {
        const __half* Aglob = g_x[t & 1] + (size_t)(mt * 128) * KDIM;

        wmma::fragment<wmma::accumulator, 16, 16, 16, float> acc[2][5];
        #pragma unroll
        for (int a = 0; a < 2; a++)
            #pragma unroll
            for (int b = 0; b < 5; b++) wmma::fill_fragment(acc[a][b], 0.f);

        auto load_chunk = [&](int kc, int bufn) {
            #pragma unroll
            for (int i = 0; i < 8; i++) {
                int idx = i * 128 + tid, row = idx >> 3, seg = idx & 7;
                cp16(&sm.u.g.A[bufn][row][seg * 8],
                     Aglob + (size_t)row * KDIM + kc * 64 + seg * 8);
            }
            #pragma unroll
            for (int i = 0; i < 5; i++) {
                int idx = i * 128 + tid, row = idx >> 3, seg = idx & 7;
                cp16(&sm.u.g.B[bufn][row][seg * 8],
                     Bglob + (size_t)row * KDIM + kc * 64 + seg * 8);
            }
        };

        load_chunk(0, 0); cp_commit();
        int buf = 0;
        for (int kc = 0; kc < NK; kc++) {
            if (kc < NK - 1) { load_chunk(kc + 1, buf ^ 1); cp_commit(); cp_wait<1>(); }
            else             { cp_wait<0>(); }
            __syncthreads();
            #pragma unroll
            for (int kk = 0; kk < 4; kk++) {
                wmma::fragment<wmma::matrix_a, 16, 16, 16, __half, wmma::row_major> fa0, fa1;
                wmma::load_matrix_sync(fa0, &sm.u.g.A[buf][warpM][kk * 16], 72);
                wmma::load_matrix_sync(fa1, &sm.u.g.A[buf][warpM + 16][kk * 16], 72);
                #pragma unroll
                for (int nf = 0; nf < 5; nf++) {
                    wmma::fragment<wmma::matrix_b, 16, 16, 16, __half, wmma::col_major> fb;
                    wmma::load_matrix_sync(fb, &sm.u.g.B[buf][nf * 16][kk * 16], 72);
                    wmma::mma_sync(acc[0][nf], fa0, fb, acc[0][nf]);
                    wmma::mma_sync(acc[1][nf], fa1, fb, acc[1][nf]);
                }
            }
            __syncthreads();
            buf ^= 1;
        }

        // ---- epilogue: stage accumulators, do LSTM cell update CTA-locally ----
        #pragma unroll
        for (int a = 0; a < 2; a++)
            #pragma unroll
            for (int nf = 0; nf < 5; nf++)
                wmma::store_matrix_sync(&sm.u.stage[warpM + a * 16][nf * 16], acc[a][nf], 84,
                                        wmma::mem_row_major);
        __syncthreads();

        {
            const int r = tid;
            const int b = mt * 128 + r;
            const float* srow = &sm.u.stage[r][0];
            if (t < TLEN) {
                __half* xn = g_x[(t + 1) & 1] + (size_t)b * KDIM;
                size_t ob = (size_t)b * (TLEN * HID) + (size_t)t * HID + hid0;
                #pragma unroll
                for (int j = 0; j < 16; j++) {
                    float bi, bff, bg, bo;
                    if (t == 0) { bi = sm.bias0[j];      bff = sm.bias0[16 + j];
                                  bg = sm.bias0[32 + j]; bo  = sm.bias0[48 + j]; }
                    else        { bi = sm.biasN[j];      bff = sm.biasN[16 + j];
                                  bg = sm.biasN[32 + j]; bo  = sm.biasN[48 + j]; }
                    float gi = srow[j]      + bi;
                    float gf = srow[16 + j] + bff;
                    float gg = srow[32 + j] + bg;
                    float go = srow[48 + j] + bo;
                    float c_old = sm.c_sm[r][j];
                    float c_new = sigf(gf) * c_old + sigf(gi) * tanhf(gg);
                    float h_new = sigf(go) * tanhf(c_new);
                    sm.c_sm[r][j] = c_new;
                    hs[ob + j] = h_new;
                    cs[ob + j] = c_new;
                    xn[hid0 + j]       = __float2half(h_new);
                    xn[HID + hid0 + j] = __float2half(c_new);
                }
            }
            if (t >= 1) {
                size_t ob2 = (size_t)b * (TLEN * HID) + (size_t)(t - 1) * HID + hid0;
                #pragma unroll
                for (int j = 0; j < 16; j++) os[ob2 + j] = srow[64 + j] + sm.biasFC[j];
            }
        }

        // ---- grid barrier (skip after last iteration) ----
        if (t < TLEN) {
            __threadfence();
            __syncthreads();
            if (tid == 0) {
                atomicAdd(&g_bar, 1u);
                unsigned target = (unsigned)NCTA * (unsigned)(t + 1);
                while (*((volatile unsigned int*)&g_bar) < target) __nanosleep(128);
            }
            __syncthreads();
        }
    }
}

// ---------------- host entry ----------------------------------------------
extern "C" void kernel_launch(void* const* d_in, const int* in_sizes, int n_in,
                              void* d_out, int out_size) {
    const float* c_vec = (const float*)d_in[0];
    const float* W_ih  = (const float*)d_in[1];
    const float* W_hh  = (const float*)d_in[2];
    const float* b_ih  = (const float*)d_in[3];
    const float* b_hh  = (const float*)d_in[4];
    const float* W_fc  = (const float*)d_in[5];
    const float* b_fc  = (const float*)d_in[6];
    float* out = (float*)d_out;

    cudaFuncSetAttribute(k_main, cudaFuncAttributeMaxDynamicSharedMemorySize,
                         (int)sizeof(MainSmem));

    k_init<<<256, 256>>>(c_vec, b_ih, b_hh);
    k_convert<<<256, 256>>>(W_ih, W_fc);
    k_fill<<<512, 256>>>(W_hh, W_fc);
    k_bcomb<<<512, 256>>>(W_ih, b_fc);
    k_wcomb<<<dim3(16, 64), 128>>>();
    k_main<<<NCTA, NTHR, sizeof(MainSmem)>>>(c_vec, b_fc, out);
}